// round 1
// baseline (speedup 1.0000x reference)
#include <cuda_runtime.h>

// Problem constants
#define H 128
#define BB 256
#define SS 1024
#define ROWS (BB*(SS-1))      // 261888
#define TM 64                 // rows per tile
#define NTILES (ROWS/TM)      // 4092 (exact)
#define HPAD 132              // padded row stride for y tile in smem

// Scratch (no cudaMalloc allowed)
__device__ float  g_A[H*H];
__device__ float  g_P0[H*H];
__device__ float  g_P1[H*H];
__device__ float  g_M[H*H];
__device__ double g_partials[NTILES];

// ---------------------------------------------------------------------------
// Stage 1: A = C^T ; P0 = I + A/4
// ---------------------------------------------------------------------------
__global__ void prep_kernel(const float* __restrict__ coeff) {
    int i = blockIdx.x, j = threadIdx.x;
    float a = coeff[j*H + i];                 // A[i][j] = C[j][i]
    g_A[i*H + j]  = a;
    g_P0[i*H + j] = ((i == j) ? 1.0f : 0.0f) + 0.25f * a;
}

// ---------------------------------------------------------------------------
// Stage 2: Horner steps for M = I + A(I + (A/2)(I + (A/3)(I + A/4)))
//   stage 0: P1 = I + (1/3) A @ P0
//   stage 1: P0 = I + (1/2) A @ P1
//   stage 2: M  = I +       A @ P0
// ---------------------------------------------------------------------------
__global__ void mm_kernel(int stage) {
    const float* X; float* out; float scale;
    if      (stage == 0) { X = g_P0; out = g_P1; scale = 1.0f/3.0f; }
    else if (stage == 1) { X = g_P1; out = g_P0; scale = 0.5f; }
    else                 { X = g_P0; out = g_M;  scale = 1.0f; }

    __shared__ float a_row[H];
    int i = blockIdx.x, j = threadIdx.x;
    a_row[j] = g_A[i*H + j];
    __syncthreads();
    float acc = 0.0f;
    #pragma unroll 16
    for (int k = 0; k < H; k++)
        acc = fmaf(a_row[k], X[k*H + j], acc);
    out[i*H + j] = ((i == j) ? 1.0f : 0.0f) + scale * acc;
}

// ---------------------------------------------------------------------------
// Stage 3: fused y1 = y@M, residual vs x1, squared-error partial sums.
// One block per 64-row tile. M (64KB) + y tile (33KB) in dynamic smem.
// 256 threads; each computes a 4x8 register tile.
// ---------------------------------------------------------------------------
__global__ void __launch_bounds__(256, 2) main_kernel(const float* __restrict__ x) {
    extern __shared__ float sh[];
    float* Msh = sh;             // [128][128]
    float* ysh = sh + H*H;       // [TM][HPAD]

    const int tid  = threadIdx.x;
    const int tile = blockIdx.x;

    // Load M into shared (vectorized)
    {
        const float4* Mg = (const float4*)g_M;
        float4* M4 = (float4*)Msh;
        #pragma unroll
        for (int i = 0; i < 16; i++)
            M4[tid + i*256] = Mg[tid + i*256];
    }
    // Load 64 y rows (x0) into shared
    {
        int row = tid >> 2, part = tid & 3;
        int rg = tile*TM + row;
        int b = rg / 1023;
        int s = rg - b*1023;
        const float4* xr = (const float4*)(x + (b*SS + s)*H);
        #pragma unroll
        for (int i = 0; i < 8; i++) {
            int c4 = part + i*4;                 // 0..31
            *(float4*)&ysh[row*HPAD + c4*4] = xr[c4];
        }
    }
    __syncthreads();

    const int tx = tid & 15, ty = tid >> 4;
    const int r0 = ty*4, j0 = tx*8;

    float acc[4][8];
    #pragma unroll
    for (int i = 0; i < 4; i++)
        #pragma unroll
        for (int j = 0; j < 8; j++) acc[i][j] = 0.0f;

    #pragma unroll 8
    for (int k = 0; k < H; k++) {
        float a0 = ysh[(r0+0)*HPAD + k];
        float a1 = ysh[(r0+1)*HPAD + k];
        float a2 = ysh[(r0+2)*HPAD + k];
        float a3 = ysh[(r0+3)*HPAD + k];
        float4 b0 = *(const float4*)&Msh[k*H + j0];
        float4 b1 = *(const float4*)&Msh[k*H + j0 + 4];
        float bv[8] = {b0.x, b0.y, b0.z, b0.w, b1.x, b1.y, b1.z, b1.w};
        #pragma unroll
        for (int j = 0; j < 8; j++) {
            acc[0][j] = fmaf(a0, bv[j], acc[0][j]);
            acc[1][j] = fmaf(a1, bv[j], acc[1][j]);
            acc[2][j] = fmaf(a2, bv[j], acc[2][j]);
            acc[3][j] = fmaf(a3, bv[j], acc[3][j]);
        }
    }

    // Epilogue: residual vs x1 and squared error
    float lsum = 0.0f;
    #pragma unroll
    for (int i = 0; i < 4; i++) {
        int rg = tile*TM + r0 + i;
        int b = rg / 1023;
        int s = rg - b*1023;
        const float4* x1r = (const float4*)(x + (b*SS + s + 1)*H);
        float4 c0 = x1r[j0/4];
        float4 c1 = x1r[j0/4 + 1];
        float d;
        d = acc[i][0] - c0.x; lsum = fmaf(d, d, lsum);
        d = acc[i][1] - c0.y; lsum = fmaf(d, d, lsum);
        d = acc[i][2] - c0.z; lsum = fmaf(d, d, lsum);
        d = acc[i][3] - c0.w; lsum = fmaf(d, d, lsum);
        d = acc[i][4] - c1.x; lsum = fmaf(d, d, lsum);
        d = acc[i][5] - c1.y; lsum = fmaf(d, d, lsum);
        d = acc[i][6] - c1.z; lsum = fmaf(d, d, lsum);
        d = acc[i][7] - c1.w; lsum = fmaf(d, d, lsum);
    }

    // Block reduction (deterministic order)
    #pragma unroll
    for (int off = 16; off; off >>= 1)
        lsum += __shfl_down_sync(0xffffffffu, lsum, off);
    __shared__ float red[8];
    int lane = tid & 31, wid = tid >> 5;
    if (lane == 0) red[wid] = lsum;
    __syncthreads();
    if (tid == 0) {
        float s = 0.0f;
        #pragma unroll
        for (int w = 0; w < 8; w++) s += red[w];
        g_partials[tile] = (double)s;
    }
}

// ---------------------------------------------------------------------------
// Stage 4: final reduction + L2 term
// ---------------------------------------------------------------------------
__global__ void finalize_kernel(const float* __restrict__ coeff,
                                float* __restrict__ out) {
    __shared__ double sd[256];
    int t = threadIdx.x;

    double s = 0.0;
    for (int i = t; i < NTILES; i += 256) s += g_partials[i];
    sd[t] = s; __syncthreads();
    for (int off = 128; off; off >>= 1) {
        if (t < off) sd[t] += sd[t + off];
        __syncthreads();
    }
    double step = sd[0];
    __syncthreads();

    double l2 = 0.0;
    for (int i = t; i < H*H; i += 256) {
        double c = (double)coeff[i];
        c = c*c;
        l2 += c*c;
    }
    sd[t] = l2; __syncthreads();
    for (int off = 128; off; off >>= 1) {
        if (t < off) sd[t] += sd[t + off];
        __syncthreads();
    }

    if (t == 0) {
        double step_loss = step / ((double)ROWS * (double)H);
        double l2_loss   = sd[0] / ((double)H * (double)H);
        out[0] = (float)(step_loss + 0.001 * l2_loss);
    }
}

// ---------------------------------------------------------------------------
extern "C" void kernel_launch(void* const* d_in, const int* in_sizes, int n_in,
                              void* d_out, int out_size) {
    const float* x     = (const float*)d_in[0];
    const float* coeff = (const float*)d_in[1];
    if (n_in >= 2 && in_sizes[0] == H*H) {   // robust to input ordering
        coeff = (const float*)d_in[0];
        x     = (const float*)d_in[1];
    }
    float* out = (float*)d_out;

    const int smem_bytes = (H*H + TM*HPAD) * (int)sizeof(float);   // 99328
    cudaFuncSetAttribute(main_kernel,
                         cudaFuncAttributeMaxDynamicSharedMemorySize, smem_bytes);

    prep_kernel<<<H, H>>>(coeff);
    mm_kernel<<<H, H>>>(0);
    mm_kernel<<<H, H>>>(1);
    mm_kernel<<<H, H>>>(2);
    main_kernel<<<NTILES, 256, smem_bytes>>>(x);
    finalize_kernel<<<1, 256>>>(coeff, out);
}

// round 4
// speedup vs baseline: 1.8848x; 1.8848x over previous
#include <cuda_runtime.h>
#include <cuda_bf16.h>
#include <cstdint>

// ---------------------------------------------------------------- constants
#define H 128
#define BB 256
#define SS 1024
#define ROWS (BB*(SS-1))          // 261888
#define TM 128                    // rows per tile
#define NTILES (ROWS/TM)          // 2046 (exact)

#define YSTR 136                  // bf16 elems per y-tile row (padded)
#define PSTR 132                  // fp32 words per P row (padded)

// dynamic smem layout (bytes)
#define SM_Y    0                         // bf16 [128][136] = 34816
#define SM_DH   34816                     // B frags hi, 32768
#define SM_DL   (SM_DH + 32768)           // B frags lo, 32768
#define SM_P    (SM_DL + 32768)           // fp32 [128][132] = 67584
#define SMEM_TOTAL (SM_P + 128*PSTR*4)    // 167936

// ---------------------------------------------------------------- scratch
__device__ float          g_B[H*H];          // C^2
__device__ float          g_C2[H*H];         // C/6 + C^2/24
__device__ __nv_bfloat16  g_DfragHi[H*H];    // D hi, mma B-fragment order
__device__ __nv_bfloat16  g_DfragLo[H*H];    // D lo, mma B-fragment order
__device__ double         g_partials[NTILES];

// ---------------------------------------------------------------- helpers
__device__ __forceinline__ uint32_t smem_u32(const void* p) {
    uint32_t a;
    asm("{ .reg .u64 t; cvta.to.shared.u64 t, %1; cvt.u32.u64 %0, t; }"
        : "=r"(a) : "l"(p));
    return a;
}

#define MMA_BF16(ACC, A0, A1, A2, A3, B0, B1)                               \
    asm volatile(                                                           \
        "mma.sync.aligned.m16n8k16.row.col.f32.bf16.bf16.f32 "              \
        "{%0,%1,%2,%3}, {%4,%5,%6,%7}, {%8,%9}, {%0,%1,%2,%3};"             \
        : "+f"((ACC)[0]), "+f"((ACC)[1]), "+f"((ACC)[2]), "+f"((ACC)[3])    \
        : "r"(A0), "r"(A1), "r"(A2), "r"(A3), "r"(B0), "r"(B1))

// ---------------------------------------------------------------- prep 1
// B = C @ C ; C2 = C/6 + B/24           (grid 32, 512 threads, smem-staged)
__global__ void __launch_bounds__(512) prep1_kernel(const float* __restrict__ coeff) {
    __shared__ float sC[H*H];
    int tid = threadIdx.x;
    {
        const float4* c4 = (const float4*)coeff;
        float4* s4 = (float4*)sC;
        #pragma unroll
        for (int i = 0; i < 8; i++) s4[tid + i*512] = c4[tid + i*512];
    }
    __syncthreads();
    int i = blockIdx.x*4 + (tid >> 7);
    int j = tid & 127;
    const float* crow = sC + i*H;
    float a0 = 0.f, a1 = 0.f, a2 = 0.f, a3 = 0.f;
    #pragma unroll
    for (int k = 0; k < H; k += 4) {
        a0 = fmaf(crow[k+0], sC[(k+0)*H + j], a0);
        a1 = fmaf(crow[k+1], sC[(k+1)*H + j], a1);
        a2 = fmaf(crow[k+2], sC[(k+2)*H + j], a2);
        a3 = fmaf(crow[k+3], sC[(k+3)*H + j], a3);
    }
    float b = (a0 + a1) + (a2 + a3);
    g_B[i*H + j]  = b;
    g_C2[i*H + j] = crow[j] * (1.0f/6.0f) + b * (1.0f/24.0f);
}

// ---------------------------------------------------------------- prep 2
// D[n][k] = (C + B/2 + C2@B)[n][k]  (= poly(C)-I, which equals the K-major
// storage of D_math for y1 = y@M with M = poly(C^T)).
// Split into bf16 hi/lo and scatter into mma.m16n8k16 B-fragment order:
//   frag u32 index = ((ks*16 + ntile)*32 + lane)*2 + reg, bf16 elem = k&1
//   lane = (n&7)*4 + ((k&7)>>1), reg = (k&15)>>3, ks = k>>4, ntile = n>>3
__global__ void __launch_bounds__(512) prep2_kernel(const float* __restrict__ coeff) {
    __shared__ float sB[H*H];
    __shared__ float sc2[4*H];
    int tid = threadIdx.x;
    {
        const float4* b4 = (const float4*)g_B;
        float4* s4 = (float4*)sB;
        #pragma unroll
        for (int i = 0; i < 8; i++) s4[tid + i*512] = b4[tid + i*512];
    }
    sc2[tid] = g_C2[(blockIdx.x*4 + (tid >> 7))*H + (tid & 127)];
    __syncthreads();

    int i = blockIdx.x*4 + (tid >> 7);     // n
    int j = tid & 127;                     // k
    const float* c2row = sc2 + (tid >> 7)*H;
    float a0 = 0.f, a1 = 0.f, a2 = 0.f, a3 = 0.f;
    #pragma unroll
    for (int k = 0; k < H; k += 4) {
        a0 = fmaf(c2row[k+0], sB[(k+0)*H + j], a0);
        a1 = fmaf(c2row[k+1], sB[(k+1)*H + j], a1);
        a2 = fmaf(c2row[k+2], sB[(k+2)*H + j], a2);
        a3 = fmaf(c2row[k+3], sB[(k+3)*H + j], a3);
    }
    float d = coeff[i*H + j] + 0.5f * sB[i*H + j] + ((a0 + a1) + (a2 + a3));
    __nv_bfloat16 hi = __float2bfloat16(d);
    __nv_bfloat16 lo = __float2bfloat16(d - __bfloat162float(hi));

    int ks = j >> 4, kin = j & 15;
    int reg = kin >> 3;
    int lane = ((i & 7) << 2) + ((kin & 7) >> 1);
    int ntile = i >> 3;
    int fidx = ((((ks*16 + ntile)*32 + lane)*2 + reg) << 1) + (j & 1);
    g_DfragHi[fidx] = hi;
    g_DfragLo[fidx] = lo;
}

// ---------------------------------------------------------------- main
// Per 128-row tile: y->bf16 smem, HMMA P = y@(Dhi+Dlo), P->smem,
// fused epilogue sum((y + P - x1)^2).
__global__ void __launch_bounds__(512, 1)
main_kernel(const float* __restrict__ x) {
    extern __shared__ char smem[];
    const int tid  = threadIdx.x;
    const int tile = blockIdx.x;

    // ---- stage D B-fragments (hi + lo), 64KB
    {
        const uint4* dh = (const uint4*)g_DfragHi;
        const uint4* dl = (const uint4*)g_DfragLo;
        uint4* sh = (uint4*)(smem + SM_DH);
        uint4* sl = (uint4*)(smem + SM_DL);
        #pragma unroll
        for (int i = 0; i < 4; i++) {
            sh[tid + i*512] = dh[tid + i*512];
            sl[tid + i*512] = dl[tid + i*512];
        }
    }

    // ---- load + convert y tile to bf16 (rows tile*128 .. +127)
    {
        int row = tid >> 2, q = tid & 3;
        int rg = tile*TM + row;
        int b  = rg / 1023;
        int s  = rg - b*1023;
        const float4* src = (const float4*)(x + (size_t)(b*SS + s)*H) + q*8;
        char* dst = smem + SM_Y + (size_t)(row*YSTR + q*32)*2;
        #pragma unroll
        for (int i = 0; i < 4; i++) {
            float4 v0 = src[2*i], v1 = src[2*i + 1];
            __nv_bfloat162 p0 = __floats2bfloat162_rn(v0.x, v0.y);
            __nv_bfloat162 p1 = __floats2bfloat162_rn(v0.z, v0.w);
            __nv_bfloat162 p2 = __floats2bfloat162_rn(v1.x, v1.y);
            __nv_bfloat162 p3 = __floats2bfloat162_rn(v1.z, v1.w);
            uint4 u;
            u.x = *(uint32_t*)&p0; u.y = *(uint32_t*)&p1;
            u.z = *(uint32_t*)&p2; u.w = *(uint32_t*)&p3;
            *(uint4*)(dst + i*16) = u;
        }
    }
    __syncthreads();

    // ---- HMMA mainloop: 16 warps; warp w: rows 16*(w&7), n-tiles 8*(w>>3)..+7
    const int w    = tid >> 5;
    const int lane = tid & 31;
    const int rb   = (w & 7) * 16;
    const int nt0  = (w >> 3) * 8;

    float acc[8][4];
    #pragma unroll
    for (int t = 0; t < 8; t++) {
        acc[t][0] = 0.f; acc[t][1] = 0.f; acc[t][2] = 0.f; acc[t][3] = 0.f;
    }

    const uint32_t sY = smem_u32(smem) + SM_Y;
    const uint32_t abase = sY + (uint32_t)((rb + (lane & 15))*YSTR + (lane >> 4)*8)*2;

    #pragma unroll
    for (int ks = 0; ks < 8; ks++) {
        uint32_t a0, a1, a2, a3;
        asm volatile("ldmatrix.sync.aligned.m8n8.x4.shared.b16 {%0,%1,%2,%3}, [%4];"
                     : "=r"(a0), "=r"(a1), "=r"(a2), "=r"(a3)
                     : "r"(abase + ks*32));
        #pragma unroll
        for (int t = 0; t < 8; t++) {
            uint32_t foff = (uint32_t)(((ks*16 + nt0 + t)*32 + lane) * 8);
            uint2 bh = *(const uint2*)(smem + SM_DH + foff);
            MMA_BF16(acc[t], a0, a1, a2, a3, bh.x, bh.y);
            uint2 bl = *(const uint2*)(smem + SM_DL + foff);
            MMA_BF16(acc[t], a0, a1, a2, a3, bl.x, bl.y);
        }
    }

    // ---- write P (fp32) to smem
    {
        float* P = (float*)(smem + SM_P);
        int r0 = rb + (lane >> 2);
        int c0 = nt0*8 + (lane & 3)*2;
        #pragma unroll
        for (int t = 0; t < 8; t++) {
            int c = c0 + t*8;
            *(float2*)&P[r0*PSTR + c]       = make_float2(acc[t][0], acc[t][1]);
            *(float2*)&P[(r0 + 8)*PSTR + c] = make_float2(acc[t][2], acc[t][3]);
        }
    }
    __syncthreads();

    // ---- epilogue: (y + P - x1)^2, fp32 y/x1 from global (L2-hot)
    float lsum = 0.f;
    {
        int row = tid >> 2, q = tid & 3;
        int rg = tile*TM + row;
        int b  = rg / 1023;
        int s  = rg - b*1023;
        const float4* yb = (const float4*)(x + (size_t)(b*SS + s)*H);
        const float*  P  = (const float*)(smem + SM_P) + row*PSTR;
        #pragma unroll
        for (int i = 0; i < 8; i++) {
            int c4 = q*8 + i;
            float4 yv = yb[c4];
            float4 xv = yb[32 + c4];          // row s+1, same batch
            float4 pv = *(const float4*)&P[c4*4];
            float d;
            d = yv.x + pv.x - xv.x; lsum = fmaf(d, d, lsum);
            d = yv.y + pv.y - xv.y; lsum = fmaf(d, d, lsum);
            d = yv.z + pv.z - xv.z; lsum = fmaf(d, d, lsum);
            d = yv.w + pv.w - xv.w; lsum = fmaf(d, d, lsum);
        }
    }

    // ---- reduction
    #pragma unroll
    for (int off = 16; off; off >>= 1)
        lsum += __shfl_down_sync(0xffffffffu, lsum, off);
    __shared__ float red[16];
    if (lane == 0) red[w] = lsum;
    __syncthreads();
    if (tid == 0) {
        float s = 0.f;
        #pragma unroll
        for (int i = 0; i < 16; i++) s += red[i];
        g_partials[tile] = (double)s;
    }
}

// ---------------------------------------------------------------- finalize
__global__ void finalize_kernel(const float* __restrict__ coeff,
                                float* __restrict__ out) {
    __shared__ double sd[256];
    int t = threadIdx.x;

    double s = 0.0;
    for (int i = t; i < NTILES; i += 256) s += g_partials[i];
    sd[t] = s; __syncthreads();
    for (int off = 128; off; off >>= 1) {
        if (t < off) sd[t] += sd[t + off];
        __syncthreads();
    }
    double step = sd[0];
    __syncthreads();

    double l2 = 0.0;
    for (int i = t; i < H*H; i += 256) {
        double c = (double)coeff[i];
        c = c * c;
        l2 += c * c;
    }
    sd[t] = l2; __syncthreads();
    for (int off = 128; off; off >>= 1) {
        if (t < off) sd[t] += sd[t + off];
        __syncthreads();
    }

    if (t == 0) {
        double step_loss = step / ((double)ROWS * (double)H);
        double l2_loss   = sd[0] / ((double)H * (double)H);
        out[0] = (float)(step_loss + 0.001 * l2_loss);
    }
}

// ---------------------------------------------------------------- launch
extern "C" void kernel_launch(void* const* d_in, const int* in_sizes, int n_in,
                              void* d_out, int out_size) {
    const float* x     = (const float*)d_in[0];
    const float* coeff = (const float*)d_in[1];
    if (n_in >= 2 && in_sizes[0] == H*H) {
        coeff = (const float*)d_in[0];
        x     = (const float*)d_in[1];
    }
    float* out = (float*)d_out;

    cudaFuncSetAttribute(main_kernel,
                         cudaFuncAttributeMaxDynamicSharedMemorySize, SMEM_TOTAL);

    prep1_kernel<<<32, 512>>>(coeff);
    prep2_kernel<<<32, 512>>>(coeff);
    main_kernel<<<NTILES, 512, SMEM_TOTAL>>>(x);
    finalize_kernel<<<1, 256>>>(coeff, out);
}

// round 5
// speedup vs baseline: 2.2039x; 1.1693x over previous
#include <cuda_runtime.h>
#include <cuda_bf16.h>
#include <cstdint>

// ---------------------------------------------------------------- constants
#define H 128
#define BB 256
#define SS 1024
#define ROWS (BB*(SS-1))          // 261888
#define TM 128                    // rows per tile
#define NTILES (ROWS/TM)          // 2046 (exact)

#define YSTR 136                  // bf16 elems per y-tile row (padded)

// dynamic smem layout (bytes)
#define SM_Y    0                         // bf16 [128][136] = 34816
#define SM_DH   34816                     // B frags hi, 32768
#define SM_DL   (SM_DH + 32768)           // B frags lo, 32768
#define SMEM_TOTAL (SM_DL + 32768)        // 100352 -> 2 CTAs/SM

// ---------------------------------------------------------------- scratch
__device__ float          g_B[H*H];          // C^2
__device__ float          g_C2[H*H];         // C/6 + C^2/24
__device__ __nv_bfloat16  g_DfragHi[H*H];    // D hi, mma B-fragment order
__device__ __nv_bfloat16  g_DfragLo[H*H];    // D lo, mma B-fragment order
__device__ double         g_partials[NTILES];
__device__ double         g_l2;              // sum C^4

// ---------------------------------------------------------------- helpers
__device__ __forceinline__ uint32_t smem_u32(const void* p) {
    uint32_t a;
    asm("{ .reg .u64 t; cvta.to.shared.u64 t, %1; cvt.u32.u64 %0, t; }"
        : "=r"(a) : "l"(p));
    return a;
}

#define MMA_BF16(ACC, A0, A1, A2, A3, B0, B1)                               \
    asm volatile(                                                           \
        "mma.sync.aligned.m16n8k16.row.col.f32.bf16.bf16.f32 "              \
        "{%0,%1,%2,%3}, {%4,%5,%6,%7}, {%8,%9}, {%0,%1,%2,%3};"             \
        : "+f"((ACC)[0]), "+f"((ACC)[1]), "+f"((ACC)[2]), "+f"((ACC)[3])    \
        : "r"(A0), "r"(A1), "r"(A2), "r"(A3), "r"(B0), "r"(B1))

// ---------------------------------------------------------------- prep 1
// B = C @ C ; C2 = C/6 + B/24 ; block 0 also computes sum(C^4) -> g_l2
__global__ void __launch_bounds__(512) prep1_kernel(const float* __restrict__ coeff) {
    __shared__ float sC[H*H];
    int tid = threadIdx.x;
    {
        const float4* c4 = (const float4*)coeff;
        float4* s4 = (float4*)sC;
        #pragma unroll
        for (int i = 0; i < 8; i++) s4[tid + i*512] = c4[tid + i*512];
    }
    __syncthreads();
    int i = blockIdx.x*4 + (tid >> 7);
    int j = tid & 127;
    const float* crow = sC + i*H;
    float a0 = 0.f, a1 = 0.f, a2 = 0.f, a3 = 0.f;
    #pragma unroll
    for (int k = 0; k < H; k += 4) {
        a0 = fmaf(crow[k+0], sC[(k+0)*H + j], a0);
        a1 = fmaf(crow[k+1], sC[(k+1)*H + j], a1);
        a2 = fmaf(crow[k+2], sC[(k+2)*H + j], a2);
        a3 = fmaf(crow[k+3], sC[(k+3)*H + j], a3);
    }
    float b = (a0 + a1) + (a2 + a3);
    g_B[i*H + j]  = b;
    g_C2[i*H + j] = crow[j] * (1.0f/6.0f) + b * (1.0f/24.0f);

    if (blockIdx.x == 0) {
        // l2 = sum over all C of C^4 (deterministic fixed-order reduction)
        double l = 0.0;
        #pragma unroll
        for (int q = 0; q < 32; q++) {
            float c = sC[tid + q*512];
            double cc = (double)c * (double)c;
            l += cc * cc;
        }
        __shared__ double sd[512];
        sd[tid] = l; __syncthreads();
        for (int off = 256; off; off >>= 1) {
            if (tid < off) sd[tid] += sd[tid + off];
            __syncthreads();
        }
        if (tid == 0) g_l2 = sd[0];
    }
}

// ---------------------------------------------------------------- prep 2
// D[n][k] = (C + B/2 + C2@B)[n][k]; split bf16 hi/lo; scatter to mma
// m16n8k16 B-fragment order:
//   fidx = ((((ks*16 + ntile)*32 + lane)*2 + reg) << 1) + (k&1)
//   lane = (n&7)*4 + ((k&7)>>1), reg = (k&15)>>3, ks = k>>4, ntile = n>>3
__global__ void __launch_bounds__(512) prep2_kernel(const float* __restrict__ coeff) {
    __shared__ float sB[H*H];
    __shared__ float sc2[4*H];
    int tid = threadIdx.x;
    {
        const float4* b4 = (const float4*)g_B;
        float4* s4 = (float4*)sB;
        #pragma unroll
        for (int i = 0; i < 8; i++) s4[tid + i*512] = b4[tid + i*512];
    }
    sc2[tid] = g_C2[(blockIdx.x*4 + (tid >> 7))*H + (tid & 127)];
    __syncthreads();

    int i = blockIdx.x*4 + (tid >> 7);     // n
    int j = tid & 127;                     // k
    const float* c2row = sc2 + (tid >> 7)*H;
    float a0 = 0.f, a1 = 0.f, a2 = 0.f, a3 = 0.f;
    #pragma unroll
    for (int k = 0; k < H; k += 4) {
        a0 = fmaf(c2row[k+0], sB[(k+0)*H + j], a0);
        a1 = fmaf(c2row[k+1], sB[(k+1)*H + j], a1);
        a2 = fmaf(c2row[k+2], sB[(k+2)*H + j], a2);
        a3 = fmaf(c2row[k+3], sB[(k+3)*H + j], a3);
    }
    float d = coeff[i*H + j] + 0.5f * sB[i*H + j] + ((a0 + a1) + (a2 + a3));
    __nv_bfloat16 hi = __float2bfloat16(d);
    __nv_bfloat16 lo = __float2bfloat16(d - __bfloat162float(hi));

    int ks = j >> 4, kin = j & 15;
    int reg = kin >> 3;
    int lane = ((i & 7) << 2) + ((kin & 7) >> 1);
    int ntile = i >> 3;
    int fidx = ((((ks*16 + ntile)*32 + lane)*2 + reg) << 1) + (j & 1);
    g_DfragHi[fidx] = hi;
    g_DfragLo[fidx] = lo;
}

// ---------------------------------------------------------------- main
// 256 threads, 2 CTAs/SM. Warp w: rows [32*(w&3), +32), n-tiles [8*(w>>2), +8).
// Per tile: y->bf16 smem; HMMA P = y@(Dhi+Dlo) in registers; epilogue
// sum((y + P - x1)^2) straight from accumulators + global y/x1.
__global__ void __launch_bounds__(256, 2)
main_kernel(const float* __restrict__ x) {
    extern __shared__ char smem[];
    const int tid  = threadIdx.x;
    const int tile = blockIdx.x;

    // ---- stage D B-fragments (hi + lo), 64KB
    {
        const uint4* dh = (const uint4*)g_DfragHi;
        const uint4* dl = (const uint4*)g_DfragLo;
        uint4* sh = (uint4*)(smem + SM_DH);
        uint4* sl = (uint4*)(smem + SM_DL);
        #pragma unroll
        for (int i = 0; i < 8; i++) {
            sh[tid + i*256] = dh[tid + i*256];
            sl[tid + i*256] = dl[tid + i*256];
        }
    }

    // ---- load + convert y tile to bf16 (rows tile*128 .. +127)
    {
        int row = tid >> 1, half = tid & 1;
        int rg = tile*TM + row;
        int b  = rg / 1023;
        int s  = rg - b*1023;
        const float4* src = (const float4*)(x + (size_t)(b*SS + s)*H) + half*16;
        char* dst = smem + SM_Y + (size_t)row*YSTR*2 + half*128;
        #pragma unroll
        for (int q = 0; q < 8; q++) {
            float4 v0 = src[2*q], v1 = src[2*q + 1];
            __nv_bfloat162 p0 = __floats2bfloat162_rn(v0.x, v0.y);
            __nv_bfloat162 p1 = __floats2bfloat162_rn(v0.z, v0.w);
            __nv_bfloat162 p2 = __floats2bfloat162_rn(v1.x, v1.y);
            __nv_bfloat162 p3 = __floats2bfloat162_rn(v1.z, v1.w);
            uint4 u;
            u.x = *(uint32_t*)&p0; u.y = *(uint32_t*)&p1;
            u.z = *(uint32_t*)&p2; u.w = *(uint32_t*)&p3;
            *(uint4*)(dst + q*16) = u;
        }
    }
    __syncthreads();

    // ---- HMMA mainloop
    const int w    = tid >> 5;
    const int lane = tid & 31;
    const int rb   = (w & 3) * 32;       // row base (2 m16 tiles)
    const int cb   = (w >> 2) * 8;       // n-tile base (8 tiles = 64 cols)

    float acc[2][8][4];
    #pragma unroll
    for (int rt = 0; rt < 2; rt++)
        #pragma unroll
        for (int t = 0; t < 8; t++) {
            acc[rt][t][0] = 0.f; acc[rt][t][1] = 0.f;
            acc[rt][t][2] = 0.f; acc[rt][t][3] = 0.f;
        }

    const uint32_t sY = smem_u32(smem) + SM_Y;
    const uint32_t abase = sY + (uint32_t)((rb + (lane & 15))*YSTR + (lane >> 4)*8)*2;

    #pragma unroll
    for (int ks = 0; ks < 8; ks++) {
        #pragma unroll
        for (int rt = 0; rt < 2; rt++) {
            uint32_t a0, a1, a2, a3;
            asm volatile("ldmatrix.sync.aligned.m8n8.x4.shared.b16 {%0,%1,%2,%3}, [%4];"
                         : "=r"(a0), "=r"(a1), "=r"(a2), "=r"(a3)
                         : "r"(abase + (uint32_t)(rt*16*YSTR*2) + ks*32));
            #pragma unroll
            for (int t = 0; t < 8; t++) {
                uint32_t foff = (uint32_t)(((ks*16 + cb + t)*32 + lane) * 8);
                uint2 bh = *(const uint2*)(smem + SM_DH + foff);
                MMA_BF16(acc[rt][t], a0, a1, a2, a3, bh.x, bh.y);
                uint2 bl = *(const uint2*)(smem + SM_DL + foff);
                MMA_BF16(acc[rt][t], a0, a1, a2, a3, bl.x, bl.y);
            }
        }
    }

    // ---- epilogue from registers: (y + P - x1)^2 ; y/x1 fp32 from global
    float lsum = 0.f;
    #pragma unroll
    for (int rt = 0; rt < 2; rt++) {
        #pragma unroll
        for (int rr = 0; rr < 2; rr++) {           // +0 / +8 row of fragment
            int r = rb + rt*16 + rr*8 + (lane >> 2);
            int rg = tile*TM + r;
            int b  = rg / 1023;
            int s  = rg - b*1023;
            const float* base = x + (size_t)(b*SS + s)*H;
            #pragma unroll
            for (int t = 0; t < 8; t++) {
                int col = (cb + t)*8 + (lane & 3)*2;
                float2 yv = *(const float2*)(base + col);
                float2 xv = *(const float2*)(base + H + col);   // row s+1
                float p0 = acc[rt][t][rr*2 + 0];
                float p1 = acc[rt][t][rr*2 + 1];
                float d;
                d = yv.x + p0 - xv.x; lsum = fmaf(d, d, lsum);
                d = yv.y + p1 - xv.y; lsum = fmaf(d, d, lsum);
            }
        }
    }

    // ---- reduction
    #pragma unroll
    for (int off = 16; off; off >>= 1)
        lsum += __shfl_down_sync(0xffffffffu, lsum, off);
    __shared__ float red[8];
    if (lane == 0) red[w] = lsum;
    __syncthreads();
    if (tid == 0) {
        float s = 0.f;
        #pragma unroll
        for (int i = 0; i < 8; i++) s += red[i];
        g_partials[tile] = (double)s;
    }
}

// ---------------------------------------------------------------- finalize
__global__ void __launch_bounds__(1024) finalize_kernel(float* __restrict__ out) {
    __shared__ double sd[1024];
    int t = threadIdx.x;
    double s = 0.0;
    if (t          < NTILES) s += g_partials[t];
    if (t + 1024   < NTILES) s += g_partials[t + 1024];
    sd[t] = s; __syncthreads();
    for (int off = 512; off; off >>= 1) {
        if (t < off) sd[t] += sd[t + off];
        __syncthreads();
    }
    if (t == 0) {
        double step_loss = sd[0] / ((double)ROWS * (double)H);
        double l2_loss   = g_l2 / ((double)H * (double)H);
        out[0] = (float)(step_loss + 0.001 * l2_loss);
    }
}

// ---------------------------------------------------------------- launch
extern "C" void kernel_launch(void* const* d_in, const int* in_sizes, int n_in,
                              void* d_out, int out_size) {
    const float* x     = (const float*)d_in[0];
    const float* coeff = (const float*)d_in[1];
    if (n_in >= 2 && in_sizes[0] == H*H) {
        coeff = (const float*)d_in[0];
        x     = (const float*)d_in[1];
    }
    float* out = (float*)d_out;

    cudaFuncSetAttribute(main_kernel,
                         cudaFuncAttributeMaxDynamicSharedMemorySize, SMEM_TOTAL);

    prep1_kernel<<<32, 512>>>(coeff);
    prep2_kernel<<<32, 512>>>(coeff);
    main_kernel<<<NTILES, 256, SMEM_TOTAL>>>(x);
    finalize_kernel<<<1, 1024>>>(out);
}

// round 7
// speedup vs baseline: 2.7814x; 1.2620x over previous
#include <cuda_runtime.h>
#include <cuda_bf16.h>
#include <cuda_fp16.h>
#include <cstdint>

// ---------------------------------------------------------------- constants
#define H 128
#define BB 256
#define SS 1024
#define ROWS (BB*(SS-1))          // 261888
#define TM 128                    // rows per tile
#define NTILES (ROWS/TM)          // 2046 (exact)

#define YSTR 136                  // fp16 elems per y-tile row (padded)

// dynamic smem layout (bytes)
#define SM_Y    0                         // fp16 [128][136] = 34816
#define SM_DF   34816                     // B frags fp16, 32768
#define SMEM_TOTAL (SM_DF + 32768)        // 67584 -> 2 CTAs/SM

// ---------------------------------------------------------------- scratch
__device__ float          g_B[H*H];          // C^2
__device__ float          g_C2[H*H];         // C/6 + C^2/24
__device__ __half         g_Dfrag[H*H];      // D fp16, mma B-fragment order
__device__ double         g_partials[NTILES];
__device__ double         g_l2;              // sum C^4
__device__ unsigned int   g_done;            // last-block counter

// ---------------------------------------------------------------- helpers
__device__ __forceinline__ uint32_t smem_u32(const void* p) {
    uint32_t a;
    asm("{ .reg .u64 t; cvta.to.shared.u64 t, %1; cvt.u32.u64 %0, t; }"
        : "=r"(a) : "l"(p));
    return a;
}

#define MMA_F16(ACC, A0, A1, A2, A3, B0, B1)                                \
    asm volatile(                                                           \
        "mma.sync.aligned.m16n8k16.row.col.f32.f16.f16.f32 "                \
        "{%0,%1,%2,%3}, {%4,%5,%6,%7}, {%8,%9}, {%0,%1,%2,%3};"             \
        : "+f"((ACC)[0]), "+f"((ACC)[1]), "+f"((ACC)[2]), "+f"((ACC)[3])    \
        : "r"(A0), "r"(A1), "r"(A2), "r"(A3), "r"(B0), "r"(B1))

// ---------------------------------------------------------------- prep 1
// B = C @ C ; C2 = C/6 + B/24 ; block 0 also computes sum(C^4) and resets g_done
__global__ void __launch_bounds__(512) prep1_kernel(const float* __restrict__ coeff) {
    __shared__ float sC[H*H];
    int tid = threadIdx.x;
    {
        const float4* c4 = (const float4*)coeff;
        float4* s4 = (float4*)sC;
        #pragma unroll
        for (int i = 0; i < 8; i++) s4[tid + i*512] = c4[tid + i*512];
    }
    __syncthreads();
    int i = blockIdx.x*4 + (tid >> 7);
    int j = tid & 127;
    const float* crow = sC + i*H;
    float a0 = 0.f, a1 = 0.f, a2 = 0.f, a3 = 0.f;
    #pragma unroll
    for (int k = 0; k < H; k += 4) {
        a0 = fmaf(crow[k+0], sC[(k+0)*H + j], a0);
        a1 = fmaf(crow[k+1], sC[(k+1)*H + j], a1);
        a2 = fmaf(crow[k+2], sC[(k+2)*H + j], a2);
        a3 = fmaf(crow[k+3], sC[(k+3)*H + j], a3);
    }
    float b = (a0 + a1) + (a2 + a3);
    g_B[i*H + j]  = b;
    g_C2[i*H + j] = crow[j] * (1.0f/6.0f) + b * (1.0f/24.0f);

    if (blockIdx.x == 0) {
        if (tid == 0) g_done = 0u;
        double l = 0.0;
        #pragma unroll
        for (int q = 0; q < 32; q++) {
            float c = sC[tid + q*512];
            double cc = (double)c * (double)c;
            l += cc * cc;
        }
        __shared__ double sd[512];
        sd[tid] = l; __syncthreads();
        for (int off = 256; off; off >>= 1) {
            if (tid < off) sd[tid] += sd[tid + off];
            __syncthreads();
        }
        if (tid == 0) g_l2 = sd[0];
    }
}

// ---------------------------------------------------------------- prep 2
// D[n][k] = (C + B/2 + C2@B)[n][k]; fp16; scatter to mma m16n8k16 B-frag order:
//   fidx = ((((ks*16 + ntile)*32 + lane)*2 + reg) << 1) + (k&1)
//   lane = (n&7)*4 + ((k&7)>>1), reg = (k&15)>>3, ks = k>>4, ntile = n>>3
__global__ void __launch_bounds__(512) prep2_kernel(const float* __restrict__ coeff) {
    __shared__ float sB[H*H];
    __shared__ float sc2[4*H];
    int tid = threadIdx.x;
    {
        const float4* b4 = (const float4*)g_B;
        float4* s4 = (float4*)sB;
        #pragma unroll
        for (int i = 0; i < 8; i++) s4[tid + i*512] = b4[tid + i*512];
    }
    sc2[tid] = g_C2[(blockIdx.x*4 + (tid >> 7))*H + (tid & 127)];
    __syncthreads();

    int i = blockIdx.x*4 + (tid >> 7);     // n
    int j = tid & 127;                     // k
    const float* c2row = sc2 + (tid >> 7)*H;
    float a0 = 0.f, a1 = 0.f, a2 = 0.f, a3 = 0.f;
    #pragma unroll
    for (int k = 0; k < H; k += 4) {
        a0 = fmaf(c2row[k+0], sB[(k+0)*H + j], a0);
        a1 = fmaf(c2row[k+1], sB[(k+1)*H + j], a1);
        a2 = fmaf(c2row[k+2], sB[(k+2)*H + j], a2);
        a3 = fmaf(c2row[k+3], sB[(k+3)*H + j], a3);
    }
    float d = coeff[i*H + j] + 0.5f * sB[i*H + j] + ((a0 + a1) + (a2 + a3));

    int ks = j >> 4, kin = j & 15;
    int reg = kin >> 3;
    int lane = ((i & 7) << 2) + ((kin & 7) >> 1);
    int ntile = i >> 3;
    int fidx = ((((ks*16 + ntile)*32 + lane)*2 + reg) << 1) + (j & 1);
    g_Dfrag[fidx] = __float2half_rn(d);
}

// ---------------------------------------------------------------- main
// 256 threads, 2 CTAs/SM. Warp w: rows [32*(w&3), +32), n-tiles [8*(w>>2), +8).
// y->fp16 smem; HMMA P = y@D in registers; epilogue sum((y + P - x1)^2);
// last CTA folds the global reduction (threadfence-reduction pattern).
__global__ void __launch_bounds__(256, 2)
main_kernel(const float* __restrict__ x, float* __restrict__ out) {
    extern __shared__ char smem[];
    const int tid  = threadIdx.x;
    const int tile = blockIdx.x;

    // ---- stage D B-fragments, 32KB
    {
        const uint4* df = (const uint4*)g_Dfrag;
        uint4* sh = (uint4*)(smem + SM_DF);
        #pragma unroll
        for (int i = 0; i < 8; i++) sh[tid + i*256] = df[tid + i*256];
    }

    // ---- load + convert y tile to fp16 (rows tile*128 .. +127)
    {
        int row = tid >> 1, half = tid & 1;
        int rg = tile*TM + row;
        int b  = rg / 1023;
        int s  = rg - b*1023;
        const float4* src = (const float4*)(x + (size_t)(b*SS + s)*H) + half*16;
        char* dst = smem + SM_Y + (size_t)row*YSTR*2 + half*128;
        #pragma unroll
        for (int q = 0; q < 8; q++) {
            float4 v0 = src[2*q], v1 = src[2*q + 1];
            __half2 p0 = __floats2half2_rn(v0.x, v0.y);
            __half2 p1 = __floats2half2_rn(v0.z, v0.w);
            __half2 p2 = __floats2half2_rn(v1.x, v1.y);
            __half2 p3 = __floats2half2_rn(v1.z, v1.w);
            uint4 u;
            u.x = *(uint32_t*)&p0; u.y = *(uint32_t*)&p1;
            u.z = *(uint32_t*)&p2; u.w = *(uint32_t*)&p3;
            *(uint4*)(dst + q*16) = u;
        }
    }
    __syncthreads();

    // ---- HMMA mainloop (single fp16 product)
    const int w    = tid >> 5;
    const int lane = tid & 31;
    const int rb   = (w & 3) * 32;       // row base (2 m16 tiles)
    const int cb   = (w >> 2) * 8;       // n-tile base (8 tiles = 64 cols)

    float acc[2][8][4];
    #pragma unroll
    for (int rt = 0; rt < 2; rt++)
        #pragma unroll
        for (int t = 0; t < 8; t++) {
            acc[rt][t][0] = 0.f; acc[rt][t][1] = 0.f;
            acc[rt][t][2] = 0.f; acc[rt][t][3] = 0.f;
        }

    const uint32_t sY = smem_u32(smem) + SM_Y;
    const uint32_t abase = sY + (uint32_t)((rb + (lane & 15))*YSTR + (lane >> 4)*8)*2;

    #pragma unroll
    for (int ks = 0; ks < 8; ks++) {
        #pragma unroll
        for (int rt = 0; rt < 2; rt++) {
            uint32_t a0, a1, a2, a3;
            asm volatile("ldmatrix.sync.aligned.m8n8.x4.shared.b16 {%0,%1,%2,%3}, [%4];"
                         : "=r"(a0), "=r"(a1), "=r"(a2), "=r"(a3)
                         : "r"(abase + (uint32_t)(rt*16*YSTR*2) + ks*32));
            #pragma unroll
            for (int t = 0; t < 8; t++) {
                uint32_t foff = (uint32_t)(((ks*16 + cb + t)*32 + lane) * 8);
                uint2 bf = *(const uint2*)(smem + SM_DF + foff);
                MMA_F16(acc[rt][t], a0, a1, a2, a3, bf.x, bf.y);
            }
        }
    }

    // ---- epilogue from registers: (y + P - x1)^2 ; y/x1 fp32 from global
    float lsum = 0.f;
    #pragma unroll
    for (int rt = 0; rt < 2; rt++) {
        #pragma unroll
        for (int rr = 0; rr < 2; rr++) {           // +0 / +8 row of fragment
            int r = rb + rt*16 + rr*8 + (lane >> 2);
            int rg = tile*TM + r;
            int b  = rg / 1023;
            int s  = rg - b*1023;
            const float* base = x + (size_t)(b*SS + s)*H;
            #pragma unroll
            for (int t = 0; t < 8; t++) {
                int col = (cb + t)*8 + (lane & 3)*2;
                float2 yv = *(const float2*)(base + col);
                float2 xv = *(const float2*)(base + H + col);   // row s+1
                float d;
                d = yv.x + acc[rt][t][rr*2+0] - xv.x; lsum = fmaf(d, d, lsum);
                d = yv.y + acc[rt][t][rr*2+1] - xv.y; lsum = fmaf(d, d, lsum);
            }
        }
    }

    // ---- CTA reduction
    #pragma unroll
    for (int off = 16; off; off >>= 1)
        lsum += __shfl_down_sync(0xffffffffu, lsum, off);
    __shared__ float red[8];
    if (lane == 0) red[w] = lsum;
    __syncthreads();

    __shared__ bool is_last;
    if (tid == 0) {
        float s = 0.f;
        #pragma unroll
        for (int i = 0; i < 8; i++) s += red[i];
        g_partials[tile] = (double)s;
        __threadfence();
        unsigned int old = atomicAdd(&g_done, 1u);
        is_last = (old == (unsigned int)(NTILES - 1));
    }
    __syncthreads();

    // ---- last CTA folds the global sum (fixed order -> deterministic)
    if (is_last) {
        double s = 0.0;
        for (int i = tid; i < NTILES; i += 256) s += g_partials[i];
        __shared__ double sd[256];
        sd[tid] = s; __syncthreads();
        for (int off = 128; off; off >>= 1) {
            if (tid < off) sd[tid] += sd[tid + off];
            __syncthreads();
        }
        if (tid == 0) {
            double step_loss = sd[0] / ((double)ROWS * (double)H);
            double l2_loss   = g_l2 / ((double)H * (double)H);
            out[0] = (float)(step_loss + 0.001 * l2_loss);
            g_done = 0u;        // reset for next graph replay
        }
    }
}

// ---------------------------------------------------------------- launch
extern "C" void kernel_launch(void* const* d_in, const int* in_sizes, int n_in,
                              void* d_out, int out_size) {
    const float* x     = (const float*)d_in[0];
    const float* coeff = (const float*)d_in[1];
    if (n_in >= 2 && in_sizes[0] == H*H) {
        coeff = (const float*)d_in[0];
        x     = (const float*)d_in[1];
    }
    float* out = (float*)d_out;

    cudaFuncSetAttribute(main_kernel,
                         cudaFuncAttributeMaxDynamicSharedMemorySize, SMEM_TOTAL);

    prep1_kernel<<<32, 512>>>(coeff);
    prep2_kernel<<<32, 512>>>(coeff);
    main_kernel<<<NTILES, 256, SMEM_TOTAL>>>(x, out);
}

// round 8
// speedup vs baseline: 2.9293x; 1.0532x over previous
#include <cuda_runtime.h>
#include <cuda_bf16.h>
#include <cuda_fp16.h>
#include <cstdint>

// ---------------------------------------------------------------- constants
#define H 128
#define BB 256
#define SS 1024
#define ROWS (BB*(SS-1))          // 261888
#define TM 128                    // rows per tile
#define NTILES (ROWS/TM)          // 2046 (exact)

#define YSTR 136                  // fp16 elems per y-tile row (padded)

// dynamic smem layout (bytes)
#define SM_Y    0                         // fp16 [128][136] = 34816
#define SM_DF   34816                     // B frags fp16, 32768
#define SMEM_TOTAL (SM_DF + 32768)        // 67584 -> 2 CTAs/SM

// ---------------------------------------------------------------- scratch
__device__ float          g_B[H*H];          // C^2
__device__ __half         g_Dfrag[H*H];      // D fp16, mma B-fragment order
__device__ double         g_partials[NTILES];
__device__ double         g_l2row[H];        // per-row sum C^4
__device__ double         g_l2;              // sum C^4
__device__ unsigned int   g_done;            // main last-block counter
__device__ unsigned int   g_bar1;            // prep phase barrier
__device__ unsigned int   g_bar2;            // prep exit counter

// ---------------------------------------------------------------- helpers
__device__ __forceinline__ uint32_t smem_u32(const void* p) {
    uint32_t a;
    asm("{ .reg .u64 t; cvta.to.shared.u64 t, %1; cvt.u32.u64 %0, t; }"
        : "=r"(a) : "l"(p));
    return a;
}

#define MMA_F16(ACC, A0, A1, A2, A3, B0, B1)                                \
    asm volatile(                                                           \
        "mma.sync.aligned.m16n8k16.row.col.f32.f16.f16.f32 "                \
        "{%0,%1,%2,%3}, {%4,%5,%6,%7}, {%8,%9}, {%0,%1,%2,%3};"             \
        : "+f"((ACC)[0]), "+f"((ACC)[1]), "+f"((ACC)[2]), "+f"((ACC)[3])    \
        : "r"(A0), "r"(A1), "r"(A2), "r"(A3), "r"(B0), "r"(B1))

// ---------------------------------------------------------------- fused prep
// grid = 128 blocks x 128 threads, all co-resident -> software global barrier.
// Block i owns row i:  phase1 B[i,:] = C[i,:]@C ; c2row = C[i,:]/6 + B[i,:]/24
//                      barrier
//                      phase2 D[i,:] = C[i,:] + B[i,:]/2 + c2row@B -> fp16 frag
__global__ void __launch_bounds__(128) prep_kernel(const float* __restrict__ coeff) {
    __shared__ float crow[H];
    __shared__ float c2row[H];
    const int i = blockIdx.x;     // row / n
    const int j = threadIdx.x;    // col / k

    crow[j] = coeff[i*H + j];
    __syncthreads();

    // ---- phase 1: b = dot(crow, C[:,j])   (column loads coalesced, L2-hot)
    float a0 = 0.f, a1 = 0.f, a2 = 0.f, a3 = 0.f;
    #pragma unroll 8
    for (int k = 0; k < H; k += 4) {
        a0 = fmaf(crow[k+0], __ldg(coeff + (k+0)*H + j), a0);
        a1 = fmaf(crow[k+1], __ldg(coeff + (k+1)*H + j), a1);
        a2 = fmaf(crow[k+2], __ldg(coeff + (k+2)*H + j), a2);
        a3 = fmaf(crow[k+3], __ldg(coeff + (k+3)*H + j), a3);
    }
    float b = (a0 + a1) + (a2 + a3);
    g_B[i*H + j]  = b;
    c2row[j] = crow[j] * (1.0f/6.0f) + b * (1.0f/24.0f);

    // per-row l2 partial (fixed order within warp-tree: deterministic)
    {
        float c = crow[j];
        float cc = c * c;
        float v = cc * cc;
        #pragma unroll
        for (int off = 16; off; off >>= 1)
            v += __shfl_down_sync(0xffffffffu, v, off);
        __shared__ float lred[4];
        if ((j & 31) == 0) lred[j >> 5] = v;
        __syncthreads();
        if (j == 0)
            g_l2row[i] = (double)((lred[0] + lred[1]) + (lred[2] + lred[3]));
    }

    // ---- global barrier (all 128 blocks resident)
    __threadfence();
    __syncthreads();
    if (j == 0) {
        atomicAdd(&g_bar1, 1u);
        while (*(volatile unsigned int*)&g_bar1 < (unsigned int)H) { }
    }
    __syncthreads();
    __threadfence();

    // ---- phase 2: d = crow[j] + b/2 + dot(c2row, B[:,j])   (B is L2-hot)
    float d0 = 0.f, d1 = 0.f, d2 = 0.f, d3 = 0.f;
    #pragma unroll 8
    for (int k = 0; k < H; k += 4) {
        d0 = fmaf(c2row[k+0], __ldg(g_B + (k+0)*H + j), d0);
        d1 = fmaf(c2row[k+1], __ldg(g_B + (k+1)*H + j), d1);
        d2 = fmaf(c2row[k+2], __ldg(g_B + (k+2)*H + j), d2);
        d3 = fmaf(c2row[k+3], __ldg(g_B + (k+3)*H + j), d3);
    }
    float d = crow[j] + 0.5f * b + ((d0 + d1) + (d2 + d3));

    // scatter to mma m16n8k16 B-fragment order (i = n, j = k)
    {
        int ks = j >> 4, kin = j & 15;
        int reg = kin >> 3;
        int lane = ((i & 7) << 2) + ((kin & 7) >> 1);
        int ntile = i >> 3;
        int fidx = ((((ks*16 + ntile)*32 + lane)*2 + reg) << 1) + (j & 1);
        g_Dfrag[fidx] = __float2half_rn(d);
    }

    // block 0: fold l2 in fixed order; also reset main's done counter
    if (i == 0 && j == 0) {
        double s = 0.0;
        #pragma unroll
        for (int r = 0; r < H; r++) s += g_l2row[r];
        g_l2 = s;
        g_done = 0u;
    }

    // ---- exit: last block resets barrier counters for the next graph replay
    __threadfence();
    __syncthreads();
    if (j == 0) {
        unsigned int old = atomicAdd(&g_bar2, 1u);
        if (old == (unsigned int)(H - 1)) { g_bar1 = 0u; g_bar2 = 0u; }
    }
}

// ---------------------------------------------------------------- main
// 256 threads, 2 CTAs/SM. Warp w: rows [32*(w&3), +32), n-tiles [8*(w>>2), +8).
// y->fp16 smem; HMMA P = y@D in registers; epilogue sum((y + P - x1)^2);
// last CTA folds the global reduction (threadfence-reduction pattern).
__global__ void __launch_bounds__(256, 2)
main_kernel(const float* __restrict__ x, float* __restrict__ out) {
    extern __shared__ char smem[];
    const int tid  = threadIdx.x;
    const int tile = blockIdx.x;

    // ---- stage D B-fragments, 32KB
    {
        const uint4* df = (const uint4*)g_Dfrag;
        uint4* sh = (uint4*)(smem + SM_DF);
        #pragma unroll
        for (int i = 0; i < 8; i++) sh[tid + i*256] = df[tid + i*256];
    }

    // ---- load + convert y tile to fp16 (rows tile*128 .. +127)
    {
        int row = tid >> 1, half = tid & 1;
        int rg = tile*TM + row;
        int b  = rg / 1023;
        int s  = rg - b*1023;
        const float4* src = (const float4*)(x + (size_t)(b*SS + s)*H) + half*16;
        char* dst = smem + SM_Y + (size_t)row*YSTR*2 + half*128;
        #pragma unroll
        for (int q = 0; q < 8; q++) {
            float4 v0 = src[2*q], v1 = src[2*q + 1];
            __half2 p0 = __floats2half2_rn(v0.x, v0.y);
            __half2 p1 = __floats2half2_rn(v0.z, v0.w);
            __half2 p2 = __floats2half2_rn(v1.x, v1.y);
            __half2 p3 = __floats2half2_rn(v1.z, v1.w);
            uint4 u;
            u.x = *(uint32_t*)&p0; u.y = *(uint32_t*)&p1;
            u.z = *(uint32_t*)&p2; u.w = *(uint32_t*)&p3;
            *(uint4*)(dst + q*16) = u;
        }
    }
    __syncthreads();

    // ---- HMMA mainloop (single fp16 product)
    const int w    = tid >> 5;
    const int lane = tid & 31;
    const int rb   = (w & 3) * 32;       // row base (2 m16 tiles)
    const int cb   = (w >> 2) * 8;       // n-tile base (8 tiles = 64 cols)

    float acc[2][8][4];
    #pragma unroll
    for (int rt = 0; rt < 2; rt++)
        #pragma unroll
        for (int t = 0; t < 8; t++) {
            acc[rt][t][0] = 0.f; acc[rt][t][1] = 0.f;
            acc[rt][t][2] = 0.f; acc[rt][t][3] = 0.f;
        }

    const uint32_t sY = smem_u32(smem) + SM_Y;
    const uint32_t abase = sY + (uint32_t)((rb + (lane & 15))*YSTR + (lane >> 4)*8)*2;

    #pragma unroll
    for (int ks = 0; ks < 8; ks++) {
        #pragma unroll
        for (int rt = 0; rt < 2; rt++) {
            uint32_t a0, a1, a2, a3;
            asm volatile("ldmatrix.sync.aligned.m8n8.x4.shared.b16 {%0,%1,%2,%3}, [%4];"
                         : "=r"(a0), "=r"(a1), "=r"(a2), "=r"(a3)
                         : "r"(abase + (uint32_t)(rt*16*YSTR*2) + ks*32));
            #pragma unroll
            for (int t = 0; t < 8; t++) {
                uint32_t foff = (uint32_t)(((ks*16 + cb + t)*32 + lane) * 8);
                uint2 bf = *(const uint2*)(smem + SM_DF + foff);
                MMA_F16(acc[rt][t], a0, a1, a2, a3, bf.x, bf.y);
            }
        }
    }

    // ---- epilogue from registers: (y + P - x1)^2 ; y/x1 fp32 from global
    float lsum = 0.f;
    #pragma unroll
    for (int rt = 0; rt < 2; rt++) {
        #pragma unroll
        for (int rr = 0; rr < 2; rr++) {           // +0 / +8 row of fragment
            int r = rb + rt*16 + rr*8 + (lane >> 2);
            int rg = tile*TM + r;
            int b  = rg / 1023;
            int s  = rg - b*1023;
            const float* base = x + (size_t)(b*SS + s)*H;
            #pragma unroll
            for (int t = 0; t < 8; t++) {
                int col = (cb + t)*8 + (lane & 3)*2;
                float2 yv = *(const float2*)(base + col);
                float2 xv = *(const float2*)(base + H + col);   // row s+1
                float d;
                d = yv.x + acc[rt][t][rr*2+0] - xv.x; lsum = fmaf(d, d, lsum);
                d = yv.y + acc[rt][t][rr*2+1] - xv.y; lsum = fmaf(d, d, lsum);
            }
        }
    }

    // ---- CTA reduction
    #pragma unroll
    for (int off = 16; off; off >>= 1)
        lsum += __shfl_down_sync(0xffffffffu, lsum, off);
    __shared__ float red[8];
    if (lane == 0) red[w] = lsum;
    __syncthreads();

    __shared__ bool is_last;
    if (tid == 0) {
        float s = 0.f;
        #pragma unroll
        for (int i = 0; i < 8; i++) s += red[i];
        g_partials[tile] = (double)s;
        __threadfence();
        unsigned int old = atomicAdd(&g_done, 1u);
        is_last = (old == (unsigned int)(NTILES - 1));
    }
    __syncthreads();

    // ---- last CTA folds the global sum (fixed order -> deterministic)
    if (is_last) {
        double s = 0.0;
        for (int i = tid; i < NTILES; i += 256) s += g_partials[i];
        __shared__ double sd[256];
        sd[tid] = s; __syncthreads();
        for (int off = 128; off; off >>= 1) {
            if (tid < off) sd[tid] += sd[tid + off];
            __syncthreads();
        }
        if (tid == 0) {
            double step_loss = sd[0] / ((double)ROWS * (double)H);
            double l2_loss   = g_l2 / ((double)H * (double)H);
            out[0] = (float)(step_loss + 0.001 * l2_loss);
        }
    }
}

// ---------------------------------------------------------------- launch
extern "C" void kernel_launch(void* const* d_in, const int* in_sizes, int n_in,
                              void* d_out, int out_size) {
    const float* x     = (const float*)d_in[0];
    const float* coeff = (const float*)d_in[1];
    if (n_in >= 2 && in_sizes[0] == H*H) {
        coeff = (const float*)d_in[0];
        x     = (const float*)d_in[1];
    }
    float* out = (float*)d_out;

    cudaFuncSetAttribute(main_kernel,
                         cudaFuncAttributeMaxDynamicSharedMemorySize, SMEM_TOTAL);

    prep_kernel<<<H, H>>>(coeff);
    main_kernel<<<NTILES, 256, SMEM_TOTAL>>>(x, out);
}